// round 13
// baseline (speedup 1.0000x reference)
#include <cuda_runtime.h>

// GC_3D loss: BCE(mean) + 1 - (1/13) * sum_k [ sum(di_k*dt_k) / (sum(dt_k^2)+1e-5) ]
// Shape (4,1,128,192,192) f32, forward-z canonical offsets.
// R13: R11 two-kernel structure + 1-deep software-pipelined prefetch in the
//      z-march (ncu showed latency-bound: fma 43.5%, issue 59%, occ 23%).

#define DX 192
#define DY 192
#define DZ 128
#define DXY (DX * DY)
#define NX4 48
#define NSUM 27
#define ZCHUNKS 8
#define ZSTEP (DZ / ZCHUNKS)   // 16
#define NBLK 2304               // 294912 threads / 128

__device__ float g_sums[NSUM];   // zero at load; finalize re-zeros after reading

__device__ __forceinline__ void ldwin(const float* __restrict__ p,
                                      int o_m1, int o_p4, float w[6]) {
    float4 v = *reinterpret_cast<const float4*>(p);
    w[0] = __ldg(p + o_m1);   // x-edge: o_m1=0 -> w[0]=center -> diff 0
    w[1] = v.x; w[2] = v.y; w[3] = v.z; w[4] = v.w;
    w[5] = __ldg(p + o_p4);   // x-edge: o_p4=3 -> w[5]=center -> diff 0
}

// One (row,dx) offset: 4 diffs per array. G: multiply dt by row flag (y-edge path only).
#define ACCUM(WI, WT, J, G, RF, D, Q) do {                                  \
    float di0 = (WI)[(J)]   - cI0; float dt0 = ((WT)[(J)]   - cT0);         \
    float di1 = (WI)[(J)+1] - cI1; float dt1 = ((WT)[(J)+1] - cT1);         \
    float di2 = (WI)[(J)+2] - cI2; float dt2 = ((WT)[(J)+2] - cT2);         \
    float di3 = (WI)[(J)+3] - cI3; float dt3 = ((WT)[(J)+3] - cT3);         \
    if (G) { dt0 *= (RF); dt1 *= (RF); dt2 *= (RF); dt3 *= (RF); }          \
    D = fmaf(di0, dt0, D); D = fmaf(di1, dt1, D);                           \
    D = fmaf(di2, dt2, D); D = fmaf(di3, dt3, D);                           \
    Q = fmaf(dt0, dt0, Q); Q = fmaf(dt1, dt1, Q);                           \
    Q = fmaf(dt2, dt2, Q); Q = fmaf(dt3, dt3, Q);                           \
} while (0)

#define ROW3(WI, WT, G, RF, K) do {                                         \
    ACCUM(WI, WT, 0, G, RF, dot[(K)],   den[(K)]);                          \
    ACCUM(WI, WT, 1, G, RF, dot[(K)+1], den[(K)+1]);                        \
    ACCUM(WI, WT, 2, G, RF, dot[(K)+2], den[(K)+2]);                        \
} while (0)

// BCE partial in log2 domain: lg2(1-i) + t*(lg2(i)-lg2(1-i))
#define BCE4(CI, CT) do {                                                   \
    float l1, l2;                                                           \
    l1 = __log2f(CI[1]); l2 = __log2f(1.0f - CI[1]); bce += l2 + CT[1]*(l1-l2); \
    l1 = __log2f(CI[2]); l2 = __log2f(1.0f - CI[2]); bce += l2 + CT[2]*(l1-l2); \
    l1 = __log2f(CI[3]); l2 = __log2f(1.0f - CI[3]); bce += l2 + CT[3]*(l1-l2); \
    l1 = __log2f(CI[4]); l2 = __log2f(1.0f - CI[4]); bce += l2 + CT[4]*(l1-l2); \
} while (0)

template<bool YG>
__device__ __forceinline__ void gc3d_march(
    const float* __restrict__ in, const float* __restrict__ tg,
    int base, int limit, int nsteps, bool do_epi,
    int o_m1, int o_p4, int dUp, int dDn,
    float fym, float fyp,
    float* dot, float* den, float& bce)
{
    float CWi[6], CWt[6], UWi[6], UWt[6];      // carried: center row, y+1 row
    ldwin(in + base,       o_m1, o_p4, CWi);
    ldwin(tg + base,       o_m1, o_p4, CWt);
    ldwin(in + base + dUp, o_m1, o_p4, UWi);
    ldwin(tg + base + dUp, o_m1, o_p4, UWt);

    // prime the pipeline: plane z0+1 rows (consumed in iteration 0)
    float PmI[6], PmT[6], PcI[6], PcT[6], PpI[6], PpT[6];
    int pb = base + DXY;
    ldwin(in + pb + dDn, o_m1, o_p4, PmI);
    ldwin(tg + pb + dDn, o_m1, o_p4, PmT);
    ldwin(in + pb,       o_m1, o_p4, PcI);
    ldwin(tg + pb,       o_m1, o_p4, PcT);
    ldwin(in + pb + dUp, o_m1, o_p4, PpI);
    ldwin(tg + pb + dUp, o_m1, o_p4, PpT);

#pragma unroll 2
    for (int s = 0; s < nsteps; ++s) {
        // prefetch plane z+2 (clamped to last plane; clamped loads unused)
        int nb = pb + DXY;
        nb = (nb > limit) ? limit : nb;
        float FmI[6], FmT[6], FcI[6], FcT[6], FpI[6], FpT[6];
        ldwin(in + nb + dDn, o_m1, o_p4, FmI);
        ldwin(tg + nb + dDn, o_m1, o_p4, FmT);
        ldwin(in + nb,       o_m1, o_p4, FcI);
        ldwin(tg + nb,       o_m1, o_p4, FcT);
        ldwin(in + nb + dUp, o_m1, o_p4, FpI);
        ldwin(tg + nb + dUp, o_m1, o_p4, FpT);

        const float cI0 = CWi[1], cI1 = CWi[2], cI2 = CWi[3], cI3 = CWi[4];
        const float cT0 = CWt[1], cT1 = CWt[2], cT2 = CWt[3], cT3 = CWt[4];

        BCE4(CWi, CWt);

        // k0: (0,0,+1) on center row — x-edges self-zero
        ACCUM(CWi, CWt, 2, false, 1.0f, dot[0], den[0]);
        // k1..3: (0,1,dx) on carried y+1 row
        ROW3(UWi, UWt, YG, fyp, 1);
        // k4..6: (1,-1,dx)
        ROW3(PmI, PmT, YG, fym, 4);
        // k7..9: (1,0,dx)
        ROW3(PcI, PcT, false, 1.0f, 7);
        // k10..12: (1,1,dx)
        ROW3(PpI, PpT, YG, fyp, 10);

#pragma unroll
        for (int j = 0; j < 6; ++j) {
            CWi[j] = PcI[j]; CWt[j] = PcT[j];
            UWi[j] = PpI[j]; UWt[j] = PpT[j];
            PmI[j] = FmI[j]; PmT[j] = FmT[j];
            PcI[j] = FcI[j]; PcT[j] = FcT[j];
            PpI[j] = FpI[j]; PpT[j] = FpT[j];
        }
        pb = nb;
    }

    if (do_epi) {  // z = 127: only dz=0 offsets; no fresh loads
        const float cI0 = CWi[1], cI1 = CWi[2], cI2 = CWi[3], cI3 = CWi[4];
        const float cT0 = CWt[1], cT1 = CWt[2], cT2 = CWt[3], cT3 = CWt[4];
        BCE4(CWi, CWt);
        ACCUM(CWi, CWt, 2, false, 1.0f, dot[0], den[0]);
        ROW3(UWi, UWt, YG, fyp, 1);
    }
}

__global__ void __launch_bounds__(128, 4) gc3d_main_kernel(
    const float* __restrict__ in, const float* __restrict__ tg)
{
    const int tid = blockIdx.x * blockDim.x + threadIdx.x;   // 0..294911
    const int x4 = tid % NX4;
    const int y  = (tid / NX4) % DY;
    const int t2 = tid / (NX4 * DY);   // 0..31
    const int zc = t2 & (ZCHUNKS - 1);
    const int b  = t2 / ZCHUNKS;
    const int z0 = zc * ZSTEP;

    const int base  = ((b * DZ + z0) * DY + y) * DX + x4 * 4;
    const int limit = ((b * DZ + (DZ - 1)) * DY + y) * DX + x4 * 4;

    const int   o_m1 = (x4 == 0)       ? 0 : -1;
    const int   o_p4 = (x4 == NX4 - 1) ? 3 : 4;
    const int   dUp  = (y == DY - 1) ? 0 : DX;
    const int   dDn  = (y == 0)      ? 0 : -DX;
    const float fyp  = (y == DY - 1) ? 0.0f : 1.0f;
    const float fym  = (y == 0)      ? 0.0f : 1.0f;

    const int  nsteps = (zc == ZCHUNKS - 1) ? (ZSTEP - 1) : ZSTEP;
    const bool do_epi = (zc == ZCHUNKS - 1);

    float dot[13], den[13], bce = 0.0f;
#pragma unroll
    for (int k = 0; k < 13; ++k) { dot[k] = 0.0f; den[k] = 0.0f; }

    if (y == 0 || y == DY - 1)
        gc3d_march<true >(in, tg, base, limit, nsteps, do_epi, o_m1, o_p4,
                          dUp, dDn, fym, fyp, dot, den, bce);
    else
        gc3d_march<false>(in, tg, base, limit, nsteps, do_epi, o_m1, o_p4,
                          dUp, dDn, fym, fyp, dot, den, bce);

    // pack 27 partials, warp butterfly, block reduce, float atomic into g_sums
    float acc[NSUM];
#pragma unroll
    for (int k = 0; k < 13; ++k) { acc[k] = dot[k]; acc[13 + k] = den[k]; }
    acc[26] = bce;

#pragma unroll
    for (int i = 0; i < NSUM; ++i) {
        float v = acc[i];
#pragma unroll
        for (int o = 16; o > 0; o >>= 1) v += __shfl_xor_sync(0xFFFFFFFFu, v, o);
        acc[i] = v;
    }

    __shared__ float sh[4][NSUM];
    const int wid = threadIdx.x >> 5;
    const int lid = threadIdx.x & 31;
    if (lid == 0) {
#pragma unroll
        for (int i = 0; i < NSUM; ++i) sh[wid][i] = acc[i];
    }
    __syncthreads();
    if (wid == 0 && lid < NSUM) {
        atomicAdd(&g_sums[lid], sh[0][lid] + sh[1][lid] + sh[2][lid] + sh[3][lid]);
    }
}

// Tiny finalize: read 27 sums, 13 parallel DP divides, write scalar,
// then re-zero g_sums so the next graph replay starts clean.
__global__ void gc3d_finalize_kernel(float* out, double inv_n) {
    const int t = threadIdx.x;

    __shared__ double sums[NSUM];
    __shared__ double ratios[13];
    if (t < NSUM) sums[t] = (double)g_sums[t];
    __syncthreads();

    if (t < 13)
        ratios[t] = sums[t] / (sums[13 + t] + 1e-5);
    __syncthreads();

    if (t == 0) {
        double accv = 0.0;
#pragma unroll
        for (int k = 0; k < 13; ++k) accv += ratios[k];
        const double bce = -sums[26] * inv_n * 0.6931471805599453; // log2 -> ln
        out[0] = (float)(bce + 1.0 - accv / 13.0);
    }

    if (t < NSUM) g_sums[t] = 0.0f;   // reset for next replay
}

extern "C" void kernel_launch(void* const* d_in, const int* in_sizes, int n_in,
                              void* d_out, int out_size)
{
    const float* in = (const float*)d_in[0];
    const float* tg = (const float*)d_in[1];
    float* out = (float*)d_out;
    const int n = in_sizes[0];   // 18874368

    gc3d_main_kernel<<<NBLK, 128>>>(in, tg);
    gc3d_finalize_kernel<<<1, 32>>>(out, 1.0 / (double)n);
}

// round 14
// speedup vs baseline: 1.1194x; 1.1194x over previous
#include <cuda_runtime.h>

// GC_3D loss: BCE(mean) + 1 - (1/13) * sum_k [ sum(di_k*dt_k) / (sum(dt_k^2)+1e-5) ]
// Shape (4,1,128,192,192) f32, forward-z canonical offsets.
// R14: eager-plane restructure — within-plane terms (BCE,k0,k1..3) computed at
//      load time, only the center row carried (12 regs + 12 movs saved, epilogue
//      gone) -> fits 5 blocks/SM (launch_bounds 128,5) for +25% occupancy.

#define DX 192
#define DY 192
#define DZ 128
#define DXY (DX * DY)
#define NX4 48
#define NSUM 27
#define ZCHUNKS 8
#define ZSTEP (DZ / ZCHUNKS)   // 16
#define NBLK 2304               // 294912 threads / 128

__device__ float g_sums[NSUM];   // zero at load; finalize re-zeros after reading

__device__ __forceinline__ void ldwin(const float* __restrict__ p,
                                      int o_m1, int o_p4, float w[6]) {
    float4 v = *reinterpret_cast<const float4*>(p);
    w[0] = __ldg(p + o_m1);   // x-edge: o_m1=0 -> w[0]=center -> diff 0
    w[1] = v.x; w[2] = v.y; w[3] = v.z; w[4] = v.w;
    w[5] = __ldg(p + o_p4);   // x-edge: o_p4=3 -> w[5]=center -> diff 0
}

// One (row,dx) offset: 4 diffs per array. G: multiply dt by row flag (y-edge path only).
#define ACCUM(WI, WT, J, G, RF, D, Q) do {                                  \
    float di0 = (WI)[(J)]   - cI0; float dt0 = ((WT)[(J)]   - cT0);         \
    float di1 = (WI)[(J)+1] - cI1; float dt1 = ((WT)[(J)+1] - cT1);         \
    float di2 = (WI)[(J)+2] - cI2; float dt2 = ((WT)[(J)+2] - cT2);         \
    float di3 = (WI)[(J)+3] - cI3; float dt3 = ((WT)[(J)+3] - cT3);         \
    if (G) { dt0 *= (RF); dt1 *= (RF); dt2 *= (RF); dt3 *= (RF); }          \
    D = fmaf(di0, dt0, D); D = fmaf(di1, dt1, D);                           \
    D = fmaf(di2, dt2, D); D = fmaf(di3, dt3, D);                           \
    Q = fmaf(dt0, dt0, Q); Q = fmaf(dt1, dt1, Q);                           \
    Q = fmaf(dt2, dt2, Q); Q = fmaf(dt3, dt3, Q);                           \
} while (0)

#define ROW3(WI, WT, G, RF, K) do {                                         \
    ACCUM(WI, WT, 0, G, RF, dot[(K)],   den[(K)]);                          \
    ACCUM(WI, WT, 1, G, RF, dot[(K)+1], den[(K)+1]);                        \
    ACCUM(WI, WT, 2, G, RF, dot[(K)+2], den[(K)+2]);                        \
} while (0)

// BCE partial in log2 domain: lg2(1-i) + t*(lg2(i)-lg2(1-i))
#define BCE4(CI, CT) do {                                                   \
    float l1, l2;                                                           \
    l1 = __log2f(CI[1]); l2 = __log2f(1.0f - CI[1]); bce += l2 + CT[1]*(l1-l2); \
    l1 = __log2f(CI[2]); l2 = __log2f(1.0f - CI[2]); bce += l2 + CT[2]*(l1-l2); \
    l1 = __log2f(CI[3]); l2 = __log2f(1.0f - CI[3]); bce += l2 + CT[3]*(l1-l2); \
    l1 = __log2f(CI[4]); l2 = __log2f(1.0f - CI[4]); bce += l2 + CT[4]*(l1-l2); \
} while (0)

// within-plane terms for a freshly loaded plane: BCE, k0 (0,0,1), k1..3 (0,1,dx)
template<bool YG>
__device__ __forceinline__ void eager_plane(
    const float Ci[6], const float Ct[6],
    const float Pi[6], const float Pt[6],
    float fyp, float* dot, float* den, float& bce)
{
    const float cI0 = Ci[1], cI1 = Ci[2], cI2 = Ci[3], cI3 = Ci[4];
    const float cT0 = Ct[1], cT1 = Ct[2], cT2 = Ct[3], cT3 = Ct[4];
    BCE4(Ci, Ct);
    ACCUM(Ci, Ct, 2, false, 1.0f, dot[0], den[0]);
    ROW3(Pi, Pt, YG, fyp, 1);
}

// dz=1 terms: carried center row of plane z vs 3 fresh rows of plane z+1
template<bool YG>
__device__ __forceinline__ void dz1_plane(
    const float Ci[6], const float Ct[6],
    const float Mi[6], const float Mt[6],
    const float Fi[6], const float Ft[6],
    const float Pi[6], const float Pt[6],
    float fym, float fyp, float* dot, float* den)
{
    const float cI0 = Ci[1], cI1 = Ci[2], cI2 = Ci[3], cI3 = Ci[4];
    const float cT0 = Ct[1], cT1 = Ct[2], cT2 = Ct[3], cT3 = Ct[4];
    ROW3(Mi, Mt, YG, fym, 4);
    ROW3(Fi, Ft, false, 1.0f, 7);
    ROW3(Pi, Pt, YG, fyp, 10);
}

template<bool YG>
__device__ __forceinline__ void gc3d_march(
    const float* __restrict__ in, const float* __restrict__ tg,
    int base, bool last,
    int o_m1, int o_p4, int dUp, int dDn,
    float fym, float fyp,
    float* dot, float* den, float& bce)
{
    float Ci[6], Ct[6];            // carried center row
    {
        float Pi[6], Pt[6];
        ldwin(in + base,       o_m1, o_p4, Ci);
        ldwin(tg + base,       o_m1, o_p4, Ct);
        ldwin(in + base + dUp, o_m1, o_p4, Pi);
        ldwin(tg + base + dUp, o_m1, o_p4, Pt);
        eager_plane<YG>(Ci, Ct, Pi, Pt, fyp, dot, den, bce);
    }

    int pb = base;
#pragma unroll 2
    for (int s = 0; s < ZSTEP - 1; ++s) {
        pb += DXY;
        float Mi[6], Mt[6], Fi[6], Ft[6], Pi[6], Pt[6];
        ldwin(in + pb + dDn, o_m1, o_p4, Mi);
        ldwin(tg + pb + dDn, o_m1, o_p4, Mt);
        ldwin(in + pb,       o_m1, o_p4, Fi);
        ldwin(tg + pb,       o_m1, o_p4, Ft);
        ldwin(in + pb + dUp, o_m1, o_p4, Pi);
        ldwin(tg + pb + dUp, o_m1, o_p4, Pt);

        eager_plane<YG>(Fi, Ft, Pi, Pt, fyp, dot, den, bce);
        dz1_plane<YG>(Ci, Ct, Mi, Mt, Fi, Ft, Pi, Pt, fym, fyp, dot, den);

#pragma unroll
        for (int j = 0; j < 6; ++j) { Ci[j] = Fi[j]; Ct[j] = Ft[j]; }
    }

    if (!last) {   // dz=1 terms for center plane z0+15 vs plane z0+16 (next chunk's)
        pb += DXY;
        float Mi[6], Mt[6], Fi[6], Ft[6], Pi[6], Pt[6];
        ldwin(in + pb + dDn, o_m1, o_p4, Mi);
        ldwin(tg + pb + dDn, o_m1, o_p4, Mt);
        ldwin(in + pb,       o_m1, o_p4, Fi);
        ldwin(tg + pb,       o_m1, o_p4, Ft);
        ldwin(in + pb + dUp, o_m1, o_p4, Pi);
        ldwin(tg + pb + dUp, o_m1, o_p4, Pt);
        dz1_plane<YG>(Ci, Ct, Mi, Mt, Fi, Ft, Pi, Pt, fym, fyp, dot, den);
    }
    // last chunk: plane 127's eager terms happened in-loop; no dz=1 at z=127.
}

__global__ void __launch_bounds__(128, 5) gc3d_main_kernel(
    const float* __restrict__ in, const float* __restrict__ tg)
{
    const int tid = blockIdx.x * blockDim.x + threadIdx.x;   // 0..294911
    const int x4 = tid % NX4;
    const int y  = (tid / NX4) % DY;
    const int t2 = tid / (NX4 * DY);   // 0..31
    const int zc = t2 & (ZCHUNKS - 1);
    const int b  = t2 / ZCHUNKS;
    const int z0 = zc * ZSTEP;

    const int base = ((b * DZ + z0) * DY + y) * DX + x4 * 4;

    const int   o_m1 = (x4 == 0)       ? 0 : -1;
    const int   o_p4 = (x4 == NX4 - 1) ? 3 : 4;
    const int   dUp  = (y == DY - 1) ? 0 : DX;
    const int   dDn  = (y == 0)      ? 0 : -DX;
    const float fyp  = (y == DY - 1) ? 0.0f : 1.0f;
    const float fym  = (y == 0)      ? 0.0f : 1.0f;

    const bool last = (zc == ZCHUNKS - 1);

    float dot[13], den[13], bce = 0.0f;
#pragma unroll
    for (int k = 0; k < 13; ++k) { dot[k] = 0.0f; den[k] = 0.0f; }

    if (y == 0 || y == DY - 1)
        gc3d_march<true >(in, tg, base, last, o_m1, o_p4, dUp, dDn,
                          fym, fyp, dot, den, bce);
    else
        gc3d_march<false>(in, tg, base, last, o_m1, o_p4, dUp, dDn,
                          fym, fyp, dot, den, bce);

    // pack 27 partials, warp butterfly, block reduce, float atomic into g_sums
    float acc[NSUM];
#pragma unroll
    for (int k = 0; k < 13; ++k) { acc[k] = dot[k]; acc[13 + k] = den[k]; }
    acc[26] = bce;

#pragma unroll
    for (int i = 0; i < NSUM; ++i) {
        float v = acc[i];
#pragma unroll
        for (int o = 16; o > 0; o >>= 1) v += __shfl_xor_sync(0xFFFFFFFFu, v, o);
        acc[i] = v;
    }

    __shared__ float sh[4][NSUM];
    const int wid = threadIdx.x >> 5;
    const int lid = threadIdx.x & 31;
    if (lid == 0) {
#pragma unroll
        for (int i = 0; i < NSUM; ++i) sh[wid][i] = acc[i];
    }
    __syncthreads();
    if (wid == 0 && lid < NSUM) {
        atomicAdd(&g_sums[lid], sh[0][lid] + sh[1][lid] + sh[2][lid] + sh[3][lid]);
    }
}

// Tiny finalize: read 27 sums, 13 parallel DP divides, write scalar,
// then re-zero g_sums so the next graph replay starts clean.
__global__ void gc3d_finalize_kernel(float* out, double inv_n) {
    const int t = threadIdx.x;

    __shared__ double sums[NSUM];
    __shared__ double ratios[13];
    if (t < NSUM) sums[t] = (double)g_sums[t];
    __syncthreads();

    if (t < 13)
        ratios[t] = sums[t] / (sums[13 + t] + 1e-5);
    __syncthreads();

    if (t == 0) {
        double accv = 0.0;
#pragma unroll
        for (int k = 0; k < 13; ++k) accv += ratios[k];
        const double bce = -sums[26] * inv_n * 0.6931471805599453; // log2 -> ln
        out[0] = (float)(bce + 1.0 - accv / 13.0);
    }

    if (t < NSUM) g_sums[t] = 0.0f;   // reset for next replay
}

extern "C" void kernel_launch(void* const* d_in, const int* in_sizes, int n_in,
                              void* d_out, int out_size)
{
    const float* in = (const float*)d_in[0];
    const float* tg = (const float*)d_in[1];
    float* out = (float*)d_out;
    const int n = in_sizes[0];   // 18874368

    gc3d_main_kernel<<<NBLK, 128>>>(in, tg);
    gc3d_finalize_kernel<<<1, 32>>>(out, 1.0 / (double)n);
}

// round 15
// speedup vs baseline: 1.2825x; 1.1457x over previous
#include <cuda_runtime.h>

// GC_3D loss: BCE(mean) + 1 - (1/13) * sum_k [ sum(di_k*dt_k) / (sum(dt_k^2)+1e-5) ]
// Shape (4,1,128,192,192) f32, forward-z canonical offsets.
// R15: R11 hot loop verbatim; block 128->64 (reg-file math: 4 blk/SM x 16 warps
//      -> 9 blk/SM x 18 warps, +12.5% resident warps, finer tail granularity).

#define DX 192
#define DY 192
#define DZ 128
#define DXY (DX * DY)
#define NX4 48
#define NSUM 27
#define ZCHUNKS 8
#define ZSTEP (DZ / ZCHUNKS)   // 16
#define THREADS 64
#define NBLK 4608               // 294912 threads / 64

__device__ float g_sums[NSUM];   // zero at load; finalize re-zeros after reading

__device__ __forceinline__ void ldwin(const float* __restrict__ p,
                                      int o_m1, int o_p4, float w[6]) {
    float4 v = *reinterpret_cast<const float4*>(p);
    w[0] = __ldg(p + o_m1);   // x-edge: o_m1=0 -> w[0]=center -> diff 0
    w[1] = v.x; w[2] = v.y; w[3] = v.z; w[4] = v.w;
    w[5] = __ldg(p + o_p4);   // x-edge: o_p4=3 -> w[5]=center -> diff 0
}

// One (row,dx) offset: 4 diffs per array. G: multiply dt by row flag (y-edge path only).
#define ACCUM(WI, WT, J, G, RF, D, Q) do {                                  \
    float di0 = (WI)[(J)]   - cI0; float dt0 = ((WT)[(J)]   - cT0);         \
    float di1 = (WI)[(J)+1] - cI1; float dt1 = ((WT)[(J)+1] - cT1);         \
    float di2 = (WI)[(J)+2] - cI2; float dt2 = ((WT)[(J)+2] - cT2);         \
    float di3 = (WI)[(J)+3] - cI3; float dt3 = ((WT)[(J)+3] - cT3);         \
    if (G) { dt0 *= (RF); dt1 *= (RF); dt2 *= (RF); dt3 *= (RF); }          \
    D = fmaf(di0, dt0, D); D = fmaf(di1, dt1, D);                           \
    D = fmaf(di2, dt2, D); D = fmaf(di3, dt3, D);                           \
    Q = fmaf(dt0, dt0, Q); Q = fmaf(dt1, dt1, Q);                           \
    Q = fmaf(dt2, dt2, Q); Q = fmaf(dt3, dt3, Q);                           \
} while (0)

#define ROW3(WI, WT, G, RF, K) do {                                         \
    ACCUM(WI, WT, 0, G, RF, dot[(K)],   den[(K)]);                          \
    ACCUM(WI, WT, 1, G, RF, dot[(K)+1], den[(K)+1]);                        \
    ACCUM(WI, WT, 2, G, RF, dot[(K)+2], den[(K)+2]);                        \
} while (0)

// BCE partial in log2 domain: lg2(1-i) + t*(lg2(i)-lg2(1-i))
#define BCE4(CI, CT) do {                                                   \
    float l1, l2;                                                           \
    l1 = __log2f(CI[1]); l2 = __log2f(1.0f - CI[1]); bce += l2 + CT[1]*(l1-l2); \
    l1 = __log2f(CI[2]); l2 = __log2f(1.0f - CI[2]); bce += l2 + CT[2]*(l1-l2); \
    l1 = __log2f(CI[3]); l2 = __log2f(1.0f - CI[3]); bce += l2 + CT[3]*(l1-l2); \
    l1 = __log2f(CI[4]); l2 = __log2f(1.0f - CI[4]); bce += l2 + CT[4]*(l1-l2); \
} while (0)

template<bool YG>
__device__ __forceinline__ void gc3d_march(
    const float* __restrict__ in, const float* __restrict__ tg,
    int base, int nsteps, bool do_epi,
    int o_m1, int o_p4, int dUp, int dDn,
    float fym, float fyp,
    float* dot, float* den, float& bce)
{
    float CWi[6], CWt[6], UWi[6], UWt[6];      // carried: center row, y+1 row
    ldwin(in + base,       o_m1, o_p4, CWi);
    ldwin(tg + base,       o_m1, o_p4, CWt);
    ldwin(in + base + dUp, o_m1, o_p4, UWi);
    ldwin(tg + base + dUp, o_m1, o_p4, UWt);

#pragma unroll 2
    for (int s = 0; s < nsteps; ++s) {
        const int baseN = base + DXY;
        float NmI[6], NmT[6], NcI[6], NcT[6], NpI[6], NpT[6];
        ldwin(in + baseN + dDn, o_m1, o_p4, NmI);
        ldwin(tg + baseN + dDn, o_m1, o_p4, NmT);
        ldwin(in + baseN,       o_m1, o_p4, NcI);
        ldwin(tg + baseN,       o_m1, o_p4, NcT);
        ldwin(in + baseN + dUp, o_m1, o_p4, NpI);
        ldwin(tg + baseN + dUp, o_m1, o_p4, NpT);

        const float cI0 = CWi[1], cI1 = CWi[2], cI2 = CWi[3], cI3 = CWi[4];
        const float cT0 = CWt[1], cT1 = CWt[2], cT2 = CWt[3], cT3 = CWt[4];

        BCE4(CWi, CWt);

        // k0: (0,0,+1) on center row — x-edges self-zero
        ACCUM(CWi, CWt, 2, false, 1.0f, dot[0], den[0]);
        // k1..3: (0,1,dx) on carried y+1 row
        ROW3(UWi, UWt, YG, fyp, 1);
        // k4..6: (1,-1,dx)
        ROW3(NmI, NmT, YG, fym, 4);
        // k7..9: (1,0,dx)
        ROW3(NcI, NcT, false, 1.0f, 7);
        // k10..12: (1,1,dx)
        ROW3(NpI, NpT, YG, fyp, 10);

#pragma unroll
        for (int j = 0; j < 6; ++j) {
            CWi[j] = NcI[j]; CWt[j] = NcT[j];
            UWi[j] = NpI[j]; UWt[j] = NpT[j];
        }
        base = baseN;
    }

    if (do_epi) {  // z = 127: only dz=0 offsets; no fresh loads
        const float cI0 = CWi[1], cI1 = CWi[2], cI2 = CWi[3], cI3 = CWi[4];
        const float cT0 = CWt[1], cT1 = CWt[2], cT2 = CWt[3], cT3 = CWt[4];
        BCE4(CWi, CWt);
        ACCUM(CWi, CWt, 2, false, 1.0f, dot[0], den[0]);
        ROW3(UWi, UWt, YG, fyp, 1);
    }
}

__global__ void __launch_bounds__(THREADS) gc3d_main_kernel(
    const float* __restrict__ in, const float* __restrict__ tg)
{
    const int tid = blockIdx.x * THREADS + threadIdx.x;   // 0..294911
    const int x4 = tid % NX4;
    const int y  = (tid / NX4) % DY;
    const int t2 = tid / (NX4 * DY);   // 0..31
    const int zc = t2 & (ZCHUNKS - 1);
    const int b  = t2 / ZCHUNKS;
    const int z0 = zc * ZSTEP;

    int base = ((b * DZ + z0) * DY + y) * DX + x4 * 4;

    const int   o_m1 = (x4 == 0)       ? 0 : -1;
    const int   o_p4 = (x4 == NX4 - 1) ? 3 : 4;
    const int   dUp  = (y == DY - 1) ? 0 : DX;
    const int   dDn  = (y == 0)      ? 0 : -DX;
    const float fyp  = (y == DY - 1) ? 0.0f : 1.0f;
    const float fym  = (y == 0)      ? 0.0f : 1.0f;

    const int  nsteps = (zc == ZCHUNKS - 1) ? (ZSTEP - 1) : ZSTEP;
    const bool do_epi = (zc == ZCHUNKS - 1);

    float dot[13], den[13], bce = 0.0f;
#pragma unroll
    for (int k = 0; k < 13; ++k) { dot[k] = 0.0f; den[k] = 0.0f; }

    if (y == 0 || y == DY - 1)
        gc3d_march<true >(in, tg, base, nsteps, do_epi, o_m1, o_p4, dUp, dDn,
                          fym, fyp, dot, den, bce);
    else
        gc3d_march<false>(in, tg, base, nsteps, do_epi, o_m1, o_p4, dUp, dDn,
                          fym, fyp, dot, den, bce);

    // pack 27 partials, warp butterfly, 2-warp block reduce, atomic into g_sums
    float acc[NSUM];
#pragma unroll
    for (int k = 0; k < 13; ++k) { acc[k] = dot[k]; acc[13 + k] = den[k]; }
    acc[26] = bce;

#pragma unroll
    for (int i = 0; i < NSUM; ++i) {
        float v = acc[i];
#pragma unroll
        for (int o = 16; o > 0; o >>= 1) v += __shfl_xor_sync(0xFFFFFFFFu, v, o);
        acc[i] = v;
    }

    __shared__ float sh[2][NSUM];
    const int wid = threadIdx.x >> 5;
    const int lid = threadIdx.x & 31;
    if (lid == 0) {
#pragma unroll
        for (int i = 0; i < NSUM; ++i) sh[wid][i] = acc[i];
    }
    __syncthreads();
    if (wid == 0 && lid < NSUM) {
        atomicAdd(&g_sums[lid], sh[0][lid] + sh[1][lid]);
    }
}

// Tiny finalize: read 27 sums, 13 parallel DP divides, write scalar,
// then re-zero g_sums so the next graph replay starts clean.
__global__ void gc3d_finalize_kernel(float* out, double inv_n) {
    const int t = threadIdx.x;

    __shared__ double sums[NSUM];
    __shared__ double ratios[13];
    if (t < NSUM) sums[t] = (double)g_sums[t];
    __syncthreads();

    if (t < 13)
        ratios[t] = sums[t] / (sums[13 + t] + 1e-5);
    __syncthreads();

    if (t == 0) {
        double accv = 0.0;
#pragma unroll
        for (int k = 0; k < 13; ++k) accv += ratios[k];
        const double bce = -sums[26] * inv_n * 0.6931471805599453; // log2 -> ln
        out[0] = (float)(bce + 1.0 - accv / 13.0);
    }

    if (t < NSUM) g_sums[t] = 0.0f;   // reset for next replay
}

extern "C" void kernel_launch(void* const* d_in, const int* in_sizes, int n_in,
                              void* d_out, int out_size)
{
    const float* in = (const float*)d_in[0];
    const float* tg = (const float*)d_in[1];
    float* out = (float*)d_out;
    const int n = in_sizes[0];   // 18874368

    gc3d_main_kernel<<<NBLK, THREADS>>>(in, tg);
    gc3d_finalize_kernel<<<1, 32>>>(out, 1.0 / (double)n);
}

// round 16
// speedup vs baseline: 1.3841x; 1.0793x over previous
#include <cuda_runtime.h>

// GC_3D loss: BCE(mean) + 1 - (1/13) * sum_k [ sum(di_k*dt_k) / (sum(dt_k^2)+1e-5) ]
// Shape (4,1,128,192,192) f32, forward-z canonical offsets.
// R16: halo values via warp shuffle (lane±1 float4 halves) instead of strided
//      scalar LDGs -> L1 wavefronts/step halved; y-guards moved from per-step
//      FMULs to one epilogue multiply, making the march warp-uniform (shfl-safe).

#define DX 192
#define DY 192
#define DZ 128
#define DXY (DX * DY)
#define NX4 48
#define NSUM 27
#define ZCHUNKS 8
#define ZSTEP (DZ / ZCHUNKS)   // 16
#define NBLK 2304               // 294912 threads / 128

__device__ float g_sums[NSUM];   // zero at load; finalize re-zeros after reading

// Window load: float4 + halos from neighbor lanes via shuffle.
// Warp lanes are consecutive x4 within a row (wraps coincide with x-edges,
// which are overridden to self -> zero diff). Warp-boundary lanes fall back
// to a single-lane predicated LDG.
__device__ __forceinline__ void ldwin_s(const float* __restrict__ p,
                                        int lane, bool xm, bool xp, float w[6]) {
    float4 v = *reinterpret_cast<const float4*>(p);
    float l = __shfl_up_sync(0xFFFFFFFFu, v.w, 1);
    float r = __shfl_down_sync(0xFFFFFFFFu, v.x, 1);
    if (lane == 0  && !xm) l = __ldg(p - 1);
    if (lane == 31 && !xp) r = __ldg(p + 4);
    if (xm) l = v.x;   // x4==0:  self -> zero diff
    if (xp) r = v.w;   // x4==47: self -> zero diff
    w[0] = l; w[1] = v.x; w[2] = v.y; w[3] = v.z; w[4] = v.w; w[5] = r;
}

// One (row,dx) offset: 4 diffs per array (no guards — applied in epilogue).
#define ACCUM(WI, WT, J, D, Q) do {                                        \
    float di0 = (WI)[(J)]   - cI0; float dt0 = ((WT)[(J)]   - cT0);        \
    float di1 = (WI)[(J)+1] - cI1; float dt1 = ((WT)[(J)+1] - cT1);        \
    float di2 = (WI)[(J)+2] - cI2; float dt2 = ((WT)[(J)+2] - cT2);        \
    float di3 = (WI)[(J)+3] - cI3; float dt3 = ((WT)[(J)+3] - cT3);        \
    D = fmaf(di0, dt0, D); D = fmaf(di1, dt1, D);                          \
    D = fmaf(di2, dt2, D); D = fmaf(di3, dt3, D);                          \
    Q = fmaf(dt0, dt0, Q); Q = fmaf(dt1, dt1, Q);                          \
    Q = fmaf(dt2, dt2, Q); Q = fmaf(dt3, dt3, Q);                          \
} while (0)

#define ROW3(WI, WT, K) do {                                               \
    ACCUM(WI, WT, 0, dot[(K)],   den[(K)]);                                \
    ACCUM(WI, WT, 1, dot[(K)+1], den[(K)+1]);                              \
    ACCUM(WI, WT, 2, dot[(K)+2], den[(K)+2]);                              \
} while (0)

// BCE partial in log2 domain: lg2(1-i) + t*(lg2(i)-lg2(1-i))
#define BCE4(CI, CT) do {                                                   \
    float l1, l2;                                                           \
    l1 = __log2f(CI[1]); l2 = __log2f(1.0f - CI[1]); bce += l2 + CT[1]*(l1-l2); \
    l1 = __log2f(CI[2]); l2 = __log2f(1.0f - CI[2]); bce += l2 + CT[2]*(l1-l2); \
    l1 = __log2f(CI[3]); l2 = __log2f(1.0f - CI[3]); bce += l2 + CT[3]*(l1-l2); \
    l1 = __log2f(CI[4]); l2 = __log2f(1.0f - CI[4]); bce += l2 + CT[4]*(l1-l2); \
} while (0)

__device__ __forceinline__ void gc3d_march(
    const float* __restrict__ in, const float* __restrict__ tg,
    int base, int nsteps, bool do_epi,
    int lane, bool xm, bool xp, int dUp, int dDn,
    float* dot, float* den, float& bce)
{
    float CWi[6], CWt[6], UWi[6], UWt[6];      // carried: center row, y+1 row
    ldwin_s(in + base,       lane, xm, xp, CWi);
    ldwin_s(tg + base,       lane, xm, xp, CWt);
    ldwin_s(in + base + dUp, lane, xm, xp, UWi);
    ldwin_s(tg + base + dUp, lane, xm, xp, UWt);

#pragma unroll 2
    for (int s = 0; s < nsteps; ++s) {
        const int baseN = base + DXY;
        float NmI[6], NmT[6], NcI[6], NcT[6], NpI[6], NpT[6];
        ldwin_s(in + baseN + dDn, lane, xm, xp, NmI);
        ldwin_s(tg + baseN + dDn, lane, xm, xp, NmT);
        ldwin_s(in + baseN,       lane, xm, xp, NcI);
        ldwin_s(tg + baseN,       lane, xm, xp, NcT);
        ldwin_s(in + baseN + dUp, lane, xm, xp, NpI);
        ldwin_s(tg + baseN + dUp, lane, xm, xp, NpT);

        const float cI0 = CWi[1], cI1 = CWi[2], cI2 = CWi[3], cI3 = CWi[4];
        const float cT0 = CWt[1], cT1 = CWt[2], cT2 = CWt[3], cT3 = CWt[4];

        BCE4(CWi, CWt);

        // k0: (0,0,+1) on center row — x-edges self-zero
        ACCUM(CWi, CWt, 2, dot[0], den[0]);
        // k1..3: (0,1,dx) on carried y+1 row  (zeroed in epilogue if y-edge)
        ROW3(UWi, UWt, 1);
        // k4..6: (1,-1,dx)
        ROW3(NmI, NmT, 4);
        // k7..9: (1,0,dx)
        ROW3(NcI, NcT, 7);
        // k10..12: (1,1,dx)
        ROW3(NpI, NpT, 10);

#pragma unroll
        for (int j = 0; j < 6; ++j) {
            CWi[j] = NcI[j]; CWt[j] = NcT[j];
            UWi[j] = NpI[j]; UWt[j] = NpT[j];
        }
        base = baseN;
    }

    if (do_epi) {  // z = 127: only dz=0 offsets; no fresh loads
        const float cI0 = CWi[1], cI1 = CWi[2], cI2 = CWi[3], cI3 = CWi[4];
        const float cT0 = CWt[1], cT1 = CWt[2], cT2 = CWt[3], cT3 = CWt[4];
        BCE4(CWi, CWt);
        ACCUM(CWi, CWt, 2, dot[0], den[0]);
        ROW3(UWi, UWt, 1);
    }
}

__global__ void __launch_bounds__(128) gc3d_main_kernel(
    const float* __restrict__ in, const float* __restrict__ tg)
{
    const int tid = blockIdx.x * blockDim.x + threadIdx.x;   // 0..294911
    const int x4 = tid % NX4;
    const int y  = (tid / NX4) % DY;
    const int t2 = tid / (NX4 * DY);   // 0..31
    const int zc = t2 & (ZCHUNKS - 1);
    const int b  = t2 / ZCHUNKS;
    const int z0 = zc * ZSTEP;

    const int base = ((b * DZ + z0) * DY + y) * DX + x4 * 4;

    const int  lane = threadIdx.x & 31;
    const bool xm   = (x4 == 0);
    const bool xp   = (x4 == NX4 - 1);
    const int  dUp  = (y == DY - 1) ? 0 : DX;
    const int  dDn  = (y == 0)      ? 0 : -DX;
    const float fyp = (y == DY - 1) ? 0.0f : 1.0f;
    const float fym = (y == 0)      ? 0.0f : 1.0f;

    const int  nsteps = (zc == ZCHUNKS - 1) ? (ZSTEP - 1) : ZSTEP;
    const bool do_epi = (zc == ZCHUNKS - 1);

    float dot[13], den[13], bce = 0.0f;
#pragma unroll
    for (int k = 0; k < 13; ++k) { dot[k] = 0.0f; den[k] = 0.0f; }

    gc3d_march(in, tg, base, nsteps, do_epi, lane, xm, xp, dUp, dDn,
               dot, den, bce);

    // apply y-row guards ONCE (k1..3,k10..12: y+1 row; k4..6: y-1 row)
#pragma unroll
    for (int k = 1; k <= 3; ++k)  { dot[k] *= fyp; den[k] *= fyp; }
#pragma unroll
    for (int k = 4; k <= 6; ++k)  { dot[k] *= fym; den[k] *= fym; }
#pragma unroll
    for (int k = 10; k <= 12; ++k){ dot[k] *= fyp; den[k] *= fyp; }

    // pack 27 partials, warp butterfly, block reduce, float atomic into g_sums
    float acc[NSUM];
#pragma unroll
    for (int k = 0; k < 13; ++k) { acc[k] = dot[k]; acc[13 + k] = den[k]; }
    acc[26] = bce;

#pragma unroll
    for (int i = 0; i < NSUM; ++i) {
        float v = acc[i];
#pragma unroll
        for (int o = 16; o > 0; o >>= 1) v += __shfl_xor_sync(0xFFFFFFFFu, v, o);
        acc[i] = v;
    }

    __shared__ float sh[4][NSUM];
    const int wid = threadIdx.x >> 5;
    if (lane == 0) {
#pragma unroll
        for (int i = 0; i < NSUM; ++i) sh[wid][i] = acc[i];
    }
    __syncthreads();
    if (wid == 0 && lane < NSUM) {
        atomicAdd(&g_sums[lane], sh[0][lane] + sh[1][lane] + sh[2][lane] + sh[3][lane]);
    }
}

// Tiny finalize: read 27 sums, 13 parallel DP divides, write scalar,
// then re-zero g_sums so the next graph replay starts clean.
__global__ void gc3d_finalize_kernel(float* out, double inv_n) {
    const int t = threadIdx.x;

    __shared__ double sums[NSUM];
    __shared__ double ratios[13];
    if (t < NSUM) sums[t] = (double)g_sums[t];
    __syncthreads();

    if (t < 13)
        ratios[t] = sums[t] / (sums[13 + t] + 1e-5);
    __syncthreads();

    if (t == 0) {
        double accv = 0.0;
#pragma unroll
        for (int k = 0; k < 13; ++k) accv += ratios[k];
        const double bce = -sums[26] * inv_n * 0.6931471805599453; // log2 -> ln
        out[0] = (float)(bce + 1.0 - accv / 13.0);
    }

    if (t < NSUM) g_sums[t] = 0.0f;   // reset for next replay
}

extern "C" void kernel_launch(void* const* d_in, const int* in_sizes, int n_in,
                              void* d_out, int out_size)
{
    const float* in = (const float*)d_in[0];
    const float* tg = (const float*)d_in[1];
    float* out = (float*)d_out;
    const int n = in_sizes[0];   // 18874368

    gc3d_main_kernel<<<NBLK, 128>>>(in, tg);
    gc3d_finalize_kernel<<<1, 32>>>(out, 1.0 / (double)n);
}